// round 6
// baseline (speedup 1.0000x reference)
#include <cuda_runtime.h>
#include <cuda_bf16.h>
#include <cstdint>

// ---------------- Problem constants ----------------
#define QLEN   2048
#define DMODEL 4096
#define NHEAD  32
#define NKVH   8
#define HEADD  128
#define NSINK  4
#define NWIN   2048
#define NSNW   (NSINK + NWIN)          // 2052
#define KTOT   (NSNW + QLEN)           // 4100
#define GRP    (NHEAD / NKVH)          // 4
#define KVDIM  (NKVH * HEADD)          // 1024

#define NEG_BIG (-3.4028234663852886e38f)   // finfo(float32).min
#define LOG10000_OVER_64 0.14391156831212787f
#define ATTN_SCALE 0.08838834764831845f     // 1/sqrt(128)

// ---------------- Scratch (device globals; no runtime alloc) ----------------
// K/V get a 64-row pad (zero-initialized, never written) so tail-tile bulk
// copies stay in-bounds; padded V rows are 0.0 so masked P (=0) * V (=0) is safe.
__device__ float g_q[QLEN * DMODEL];        // q proj -> RoPE'd, tf32-rounded
__device__ float g_kproj[QLEN * KVDIM];
__device__ float g_vproj[QLEN * KVDIM];
__device__ float g_K[NKVH * KTOT * HEADD + 64 * HEADD];  // RoPE'd K, d-interleaved, tf32
__device__ float g_V[NKVH * KTOT * HEADD + 64 * HEADD];  // V cache, tf32
__device__ float g_attn[QLEN * DMODEL];     // attention output (pre-Wo)
__device__ float g_bias[NSNW];              // cache bias (mask * NEG)
__device__ int   g_maxpos;

__device__ __forceinline__ float neg_inf() { return __int_as_float(0xff800000u); }

// column interleave within each 8-block: pairs (c, c+4) adjacent
__device__ __forceinline__ int perm8(int d) {
    return (d & ~7) | ((d & 3) << 1) | ((d >> 2) & 1);
}

__device__ __forceinline__ uint32_t f2tf32(float x) {
    uint32_t u;
    asm("cvt.rna.tf32.f32 %0, %1;" : "=r"(u) : "f"(x));
    return u;
}
__device__ __forceinline__ float f2tf32f(float x) {
    return __uint_as_float(f2tf32(x));
}

__device__ __forceinline__ void mma_tf32(float d[4],
                                         uint32_t a0, uint32_t a1, uint32_t a2, uint32_t a3,
                                         uint32_t b0, uint32_t b1) {
    asm volatile(
        "mma.sync.aligned.m16n8k8.row.col.f32.tf32.tf32.f32 "
        "{%0,%1,%2,%3}, {%4,%5,%6,%7}, {%8,%9}, {%0,%1,%2,%3};\n"
        : "+f"(d[0]), "+f"(d[1]), "+f"(d[2]), "+f"(d[3])
        : "r"(a0), "r"(a1), "r"(a2), "r"(a3), "r"(b0), "r"(b1));
}

// ---------------- mbarrier + bulk-async helpers ----------------
__device__ __forceinline__ void mbar_init(uint32_t addr, uint32_t cnt) {
    asm volatile("mbarrier.init.shared.b64 [%0], %1;" :: "r"(addr), "r"(cnt) : "memory");
}
__device__ __forceinline__ void mbar_expect(uint32_t addr, uint32_t tx) {
    asm volatile("mbarrier.arrive.expect_tx.shared.b64 _, [%0], %1;"
                 :: "r"(addr), "r"(tx) : "memory");
}
__device__ __forceinline__ void mbar_wait(uint32_t addr, uint32_t phase) {
    asm volatile(
        "{\n\t"
        ".reg .pred P;\n\t"
        "LAB_WAIT%=:\n\t"
        "mbarrier.try_wait.parity.acquire.cta.shared::cta.b64 P, [%0], %1, 0x989680;\n\t"
        "@P bra LAB_DONE%=;\n\t"
        "bra LAB_WAIT%=;\n\t"
        "LAB_DONE%=:\n\t"
        "}"
        :: "r"(addr), "r"(phase) : "memory");
}
__device__ __forceinline__ void bulk_g2s(uint32_t dst, const void* src,
                                         uint32_t bytes, uint32_t mbar) {
    asm volatile(
        "cp.async.bulk.shared::cluster.global.mbarrier::complete_tx::bytes "
        "[%0], [%1], %2, [%3];"
        :: "r"(dst), "l"(src), "r"(bytes), "r"(mbar) : "memory");
}

// ---------------- max position + bias precompute ----------------
__global__ void maxpos_kernel(const int* __restrict__ sink_pos,
                              const int* __restrict__ key_pos) {
    __shared__ int sm[256];
    int tid = threadIdx.x;
    int v = -2147483647;
    for (int i = tid; i < NWIN; i += 256) v = max(v, key_pos[i]);
    for (int i = tid; i < NSINK; i += 256) v = max(v, sink_pos[i]);
    sm[tid] = v;
    __syncthreads();
    for (int s = 128; s > 0; s >>= 1) {
        if (tid < s) sm[tid] = max(sm[tid], sm[tid + s]);
        __syncthreads();
    }
    if (tid == 0) g_maxpos = sm[0] + 1;
}

__global__ void bias_kernel(const float* __restrict__ sink_mask,
                            const float* __restrict__ key_mask) {
    int i = blockIdx.x * blockDim.x + threadIdx.x;
    if (i >= NSNW) return;
    float m = (i < NSINK) ? sink_mask[i] : key_mask[i - NSINK];
    g_bias[i] = m * NEG_BIG;
}

// ---------------- TF32 tensor-core GEMM (unchanged from R4) ----------------
#define GSTR 136
__global__ void __launch_bounds__(256, 2) gemm_tf32(
    const float* __restrict__ A, const float* __restrict__ B,
    float* __restrict__ C, int M, int N, int K) {
    __shared__ uint32_t As[32][GSTR];   // As[k][m]
    __shared__ uint32_t Bs[32][GSTR];   // Bs[k][n]

    const int tid  = threadIdx.x;
    const int lane = tid & 31;
    const int warp = tid >> 5;
    const int wm   = (warp >> 1) * 32;
    const int wn   = (warp & 1) * 64;
    const int cRow = blockIdx.y * 128;
    const int cCol = blockIdx.x * 128;
    const int r0   = lane >> 2;
    const int cq   = lane & 3;

    float acc[2][8][4];
#pragma unroll
    for (int mt = 0; mt < 2; mt++)
#pragma unroll
        for (int nt = 0; nt < 8; nt++)
#pragma unroll
            for (int f = 0; f < 4; f++) acc[mt][nt][f] = 0.f;

    for (int k0 = 0; k0 < K; k0 += 32) {
#pragma unroll
        for (int i = 0; i < 4; i++) {          // A tile: 128 x 32
            int e = (i * 256 + tid) * 4;
            int r = e >> 5, c = e & 31;
            float4 v = *(const float4*)(A + (size_t)(cRow + r) * K + k0 + c);
            As[c + 0][r] = f2tf32(v.x);
            As[c + 1][r] = f2tf32(v.y);
            As[c + 2][r] = f2tf32(v.z);
            As[c + 3][r] = f2tf32(v.w);
        }
#pragma unroll
        for (int i = 0; i < 4; i++) {          // B tile: 32 x 128
            int e = (i * 256 + tid) * 4;
            int r = e >> 7, c = e & 127;
            float4 v = *(const float4*)(B + (size_t)(k0 + r) * N + cCol + c);
            uint4 u = {f2tf32(v.x), f2tf32(v.y), f2tf32(v.z), f2tf32(v.w)};
            *(uint4*)&Bs[r][c] = u;
        }
        __syncthreads();

#pragma unroll
        for (int kk = 0; kk < 4; kk++) {
            const int kb = kk * 8;
            uint32_t af[2][4];
#pragma unroll
            for (int mt = 0; mt < 2; mt++) {
                int mr = wm + mt * 16 + r0;
                af[mt][0] = As[kb + cq][mr];
                af[mt][1] = As[kb + cq][mr + 8];
                af[mt][2] = As[kb + 4 + cq][mr];
                af[mt][3] = As[kb + 4 + cq][mr + 8];
            }
#pragma unroll
            for (int nt = 0; nt < 8; nt++) {
                int nc = wn + nt * 8 + r0;
                uint32_t b0 = Bs[kb + cq][nc];
                uint32_t b1 = Bs[kb + 4 + cq][nc];
                mma_tf32(acc[0][nt], af[0][0], af[0][1], af[0][2], af[0][3], b0, b1);
                mma_tf32(acc[1][nt], af[1][0], af[1][1], af[1][2], af[1][3], b0, b1);
            }
        }
        __syncthreads();
    }

#pragma unroll
    for (int mt = 0; mt < 2; mt++)
#pragma unroll
        for (int nt = 0; nt < 8; nt++) {
            int r = cRow + wm + mt * 16 + r0;
            int c = cCol + wn + nt * 8 + cq * 2;
            float2 v0 = {acc[mt][nt][0], acc[mt][nt][1]};
            float2 v1 = {acc[mt][nt][2], acc[mt][nt][3]};
            *(float2*)(C + (size_t)r * N + c)       = v0;
            *(float2*)(C + (size_t)(r + 8) * N + c) = v1;
        }
}

// ---------------- RoPE on q (in place, writes tf32-rounded) ----------------
__global__ void rope_q_kernel() {
    int idx = blockIdx.x * blockDim.x + threadIdx.x;
    if (idx >= QLEN * NHEAD * 64) return;
    int i  = idx & 63;
    int hq = idx >> 6;
    int h  = hq & (NHEAD - 1);
    int t  = hq >> 5;
    float* p = g_q + (size_t)t * DMODEL + h * HEADD;
    float pos = (float)(g_maxpos + t);
    float freq = expf(-(float)i * LOG10000_OVER_64);
    float ang = pos * freq;
    float c, s;
    sincosf(ang, &s, &c);
    float x1 = p[i], x2 = p[i + 64];
    p[i]      = f2tf32f(x1 * c - x2 * s);
    p[i + 64] = f2tf32f(x2 * c + x1 * s);
}

// ---------------- Build concatenated K (RoPE'd, d-interleaved) and V caches ----------------
__global__ void build_cache_kernel(const float* __restrict__ sink_k,
                                   const float* __restrict__ sink_v,
                                   const float* __restrict__ win_k,
                                   const float* __restrict__ win_v,
                                   const int* __restrict__ sink_pos,
                                   const int* __restrict__ key_pos) {
    int idx = blockIdx.x * blockDim.x + threadIdx.x;
    if (idx >= NKVH * KTOT * 64) return;
    int i   = idx & 63;
    int rj  = idx >> 6;
    int j   = rj % KTOT;
    int kvh = rj / KTOT;

    const float* kp;
    const float* vp;
    int pos;
    if (j < NSINK) {
        kp = sink_k + (size_t)(kvh * NSINK + j) * HEADD;
        vp = sink_v + (size_t)(kvh * NSINK + j) * HEADD;
        pos = sink_pos[j];
    } else if (j < NSNW) {
        int w = j - NSINK;
        kp = win_k + (size_t)(kvh * NWIN + w) * HEADD;
        vp = win_v + (size_t)(kvh * NWIN + w) * HEADD;
        pos = key_pos[w];
    } else {
        int t = j - NSNW;
        kp = g_kproj + (size_t)t * KVDIM + kvh * HEADD;
        vp = g_vproj + (size_t)t * KVDIM + kvh * HEADD;
        pos = g_maxpos + t;
    }

    float freq = expf(-(float)i * LOG10000_OVER_64);
    float ang = (float)pos * freq;
    float c, s;
    sincosf(ang, &s, &c);
    float x1 = kp[i], x2 = kp[i + 64];

    size_t out = ((size_t)kvh * KTOT + j) * HEADD;
    g_K[out + perm8(i)]      = f2tf32f(x1 * c - x2 * s);
    g_K[out + perm8(i + 64)] = f2tf32f(x2 * c + x1 * s);
    g_V[out + i]      = f2tf32f(vp[i]);
    g_V[out + i + 64] = f2tf32f(vp[i + 64]);
}

// ---------------- Flash attention v4: bulk-async K/V, LDS.64 fragments ----------------
// Smem word layout (dynamic):
//   buf0: Ks0[64][136] @ 0        Vs0[64][136] @ 8704
//   buf1: Ks1[64][136] @ 17408    Vs1[64][136] @ 26112
//   (Q staged in buf1 region during prologue: 128*136 = 17408 words, exact fit)
//   Ps[128][68] @ 34816 (8704 w)
//   mbar[2] @ 43520 words (16B aligned)
#define KS_STR 136
#define VS_STR 136
#define PS_STR 68
#define BUF_WORDS (64 * KS_STR + 64 * VS_STR)      // 17408
#define PS_OFF    (2 * BUF_WORDS)                   // 34816
#define MBAR_OFF  (PS_OFF + 128 * PS_STR)           // 43520
#define ATTN_SMEM_BYTES (MBAR_OFF * 4 + 16)

__device__ __forceinline__ void issue_tile(uint32_t smem_base, int buf,
                                           uint32_t mbar,
                                           const float* Kg, const float* Vg, int j0) {
    mbar_expect(mbar, 64 * 1024);           // 64 rows x (512B K + 512B V)
    uint32_t kdst = smem_base + buf * (BUF_WORDS * 4);
    uint32_t vdst = kdst + 64 * KS_STR * 4;
    const float* ks = Kg + (size_t)j0 * HEADD;
    const float* vs = Vg + (size_t)j0 * HEADD;
#pragma unroll 4
    for (int r = 0; r < 64; r++) {
        bulk_g2s(kdst + r * (KS_STR * 4), ks + r * HEADD, 512, mbar);
        bulk_g2s(vdst + r * (VS_STR * 4), vs + r * HEADD, 512, mbar);
    }
}

__global__ void __launch_bounds__(256, 1) attn_mma_kernel() {
    extern __shared__ uint32_t smw[];
    const uint32_t smem_base = (uint32_t)__cvta_generic_to_shared(smw);
    const uint32_t mbar_base = smem_base + MBAR_OFF * 4;

    const int h    = blockIdx.x;
    const int kvh  = h >> 2;                              // GRP = 4
    const int qt0  = (gridDim.y - 1 - blockIdx.y) * 128;  // long blocks first
    const int tid  = threadIdx.x;
    const int lane = tid & 31;
    const int warp = tid >> 5;
    const int qw   = warp * 16;
    const int r0   = lane >> 2;
    const int cq   = lane & 3;

    const float* Kg = g_K + (size_t)kvh * KTOT * HEADD;
    const float* Vg = g_V + (size_t)kvh * KTOT * HEADD;

    int kmax = NSNW + qt0 + 128;
    if (kmax > KTOT) kmax = KTOT;
    const int ntiles = (kmax + 63) >> 6;

    if (tid == 0) {
        mbar_init(mbar_base, 1);
        mbar_init(mbar_base + 8, 1);
    }
    __syncthreads();

    // kick off tile 0 into buf0 (async; overlaps Q staging)
    if (tid == 0) issue_tile(smem_base, 0, mbar_base, Kg, Vg, 0);

    // ---- stage Q tile [128q][128d] into buf1 region, d-interleaved ----
    {
        uint32_t* Qs = smw + BUF_WORDS;
        const float* qg = g_q + (size_t)qt0 * DMODEL + h * HEADD;
        for (int i = tid; i < 128 * 32; i += 256) {
            int q = i >> 5, c4 = (i & 31) * 4;
            float4 v = *(const float4*)(qg + (size_t)q * DMODEL + c4);
            uint32_t* qrow = Qs + q * KS_STR;
            qrow[perm8(c4 + 0)] = __float_as_uint(v.x);
            qrow[perm8(c4 + 1)] = __float_as_uint(v.y);
            qrow[perm8(c4 + 2)] = __float_as_uint(v.z);
            qrow[perm8(c4 + 3)] = __float_as_uint(v.w);
        }
    }
    __syncthreads();

    // ---- extract Q fragments to registers (LDS.64 pairs) ----
    uint32_t QA[16][4];
    {
        const uint32_t* Qs = smw + BUF_WORDS;
#pragma unroll
        for (int kk = 0; kk < 16; kk++) {
            uint2 u0 = *(const uint2*)&Qs[(qw + r0) * KS_STR + kk * 8 + 2 * cq];
            uint2 u1 = *(const uint2*)&Qs[(qw + r0 + 8) * KS_STR + kk * 8 + 2 * cq];
            QA[kk][0] = u0.x; QA[kk][1] = u1.x;
            QA[kk][2] = u0.y; QA[kk][3] = u1.y;
        }
    }
    __syncthreads();

    float O[16][4];
#pragma unroll
    for (int nt = 0; nt < 16; nt++)
#pragma unroll
        for (int f = 0; f < 4; f++) O[nt][f] = 0.f;
    float m0 = neg_inf(), m1 = neg_inf(), l0 = 0.f, l1 = 0.f;

    const int q0 = qt0 + qw + r0;
    const int q1 = q0 + 8;

    for (int t = 0; t < ntiles; t++) {
        const int j0 = t * 64;
        const int buf = t & 1;
        const uint32_t* Ks = smw + buf * BUF_WORDS;
        const uint32_t* Vs = Ks + 64 * KS_STR;
        uint32_t* Ps = smw + PS_OFF;

        // wait for this tile's K/V data (parity flips every 2 tiles per buffer)
        mbar_wait(mbar_base + buf * 8, (t >> 1) & 1);
        __syncthreads();   // all warps past wait AND done reading other buf (prev iter)

        // prefetch next tile into the other buffer
        if (t + 1 < ntiles && tid == 0)
            issue_tile(smem_base, buf ^ 1, mbar_base + (buf ^ 1) * 8, Kg, Vg, j0 + 64);

        // preload bias for this tile's columns
        float bb[8][2];
#pragma unroll
        for (int nt = 0; nt < 8; nt++) {
            int ja = j0 + nt * 8 + cq * 2;
            bb[nt][0] = (ja < NSNW) ? g_bias[ja] : 0.f;
            bb[nt][1] = (ja + 1 < NSNW) ? g_bias[ja + 1] : 0.f;
        }

        // ---- S = Q @ K^T  (16 x 64 per warp) ----
        float S[8][4];
#pragma unroll
        for (int nt = 0; nt < 8; nt++)
#pragma unroll
            for (int f = 0; f < 4; f++) S[nt][f] = 0.f;

#pragma unroll
        for (int kk = 0; kk < 16; kk++) {
            const int kb = kk * 8;
#pragma unroll
            for (int nt = 0; nt < 8; nt++) {
                uint2 b = *(const uint2*)&Ks[(nt * 8 + r0) * KS_STR + kb + 2 * cq];
                mma_tf32(S[nt], QA[kk][0], QA[kk][1], QA[kk][2], QA[kk][3], b.x, b.y);
            }
        }

        // ---- online softmax ----
        float rm0 = neg_inf(), rm1 = neg_inf();
#pragma unroll
        for (int nt = 0; nt < 8; nt++) {
            int ja = j0 + nt * 8 + cq * 2;
            int jb = ja + 1;
            float s0 = (ja <= q0 + NSNW) ? S[nt][0] * ATTN_SCALE + bb[nt][0] : neg_inf();
            float s1 = (jb <= q0 + NSNW) ? S[nt][1] * ATTN_SCALE + bb[nt][1] : neg_inf();
            float s2 = (ja <= q1 + NSNW) ? S[nt][2] * ATTN_SCALE + bb[nt][0] : neg_inf();
            float s3 = (jb <= q1 + NSNW) ? S[nt][3] * ATTN_SCALE + bb[nt][1] : neg_inf();
            S[nt][0] = s0; S[nt][1] = s1; S[nt][2] = s2; S[nt][3] = s3;
            rm0 = fmaxf(rm0, fmaxf(s0, s1));
            rm1 = fmaxf(rm1, fmaxf(s2, s3));
        }
        rm0 = fmaxf(rm0, __shfl_xor_sync(0xffffffffu, rm0, 1));
        rm0 = fmaxf(rm0, __shfl_xor_sync(0xffffffffu, rm0, 2));
        rm1 = fmaxf(rm1, __shfl_xor_sync(0xffffffffu, rm1, 1));
        rm1 = fmaxf(rm1, __shfl_xor_sync(0xffffffffu, rm1, 2));

        float mn0 = fmaxf(m0, rm0);
        float mn1 = fmaxf(m1, rm1);
        float mns0 = (mn0 == neg_inf()) ? 0.f : mn0;
        float mns1 = (mn1 == neg_inf()) ? 0.f : mn1;
        float f0 = __expf(m0 - mns0);
        float f1 = __expf(m1 - mns1);
        if (m0 == neg_inf()) f0 = 0.f;
        if (m1 == neg_inf()) f1 = 0.f;
        m0 = mn0; m1 = mn1;
        l0 *= f0; l1 *= f1;
#pragma unroll
        for (int nt = 0; nt < 16; nt++) {
            O[nt][0] *= f0; O[nt][1] *= f0;
            O[nt][2] *= f1; O[nt][3] *= f1;
        }

        float ps0 = 0.f, ps1 = 0.f;
#pragma unroll
        for (int nt = 0; nt < 8; nt++) {
            int col = nt * 8 + cq * 2;
            float p0 = __expf(S[nt][0] - mns0);
            float p1 = __expf(S[nt][1] - mns0);
            float p2 = __expf(S[nt][2] - mns1);
            float p3 = __expf(S[nt][3] - mns1);
            ps0 += p0 + p1;
            ps1 += p2 + p3;
            *(uint2*)&Ps[(qw + r0) * PS_STR + col]     = make_uint2(f2tf32(p0), f2tf32(p1));
            *(uint2*)&Ps[(qw + r0 + 8) * PS_STR + col] = make_uint2(f2tf32(p2), f2tf32(p3));
        }
        ps0 += __shfl_xor_sync(0xffffffffu, ps0, 1);
        ps0 += __shfl_xor_sync(0xffffffffu, ps0, 2);
        ps1 += __shfl_xor_sync(0xffffffffu, ps1, 1);
        ps1 += __shfl_xor_sync(0xffffffffu, ps1, 2);
        l0 += ps0; l1 += ps1;

        __syncwarp();

        // ---- O += P @ V ----
#pragma unroll
        for (int kk = 0; kk < 8; kk++) {
            const int kb = kk * 8;
            uint32_t a0 = Ps[(qw + r0) * PS_STR + kb + cq];
            uint32_t a1 = Ps[(qw + r0 + 8) * PS_STR + kb + cq];
            uint32_t a2 = Ps[(qw + r0) * PS_STR + kb + cq + 4];
            uint32_t a3 = Ps[(qw + r0 + 8) * PS_STR + kb + cq + 4];
#pragma unroll
            for (int nt = 0; nt < 16; nt++) {
                uint32_t b0 = Vs[(kb + cq) * VS_STR + nt * 8 + r0];
                uint32_t b1 = Vs[(kb + cq + 4) * VS_STR + nt * 8 + r0];
                mma_tf32(O[nt], a0, a1, a2, a3, b0, b1);
            }
        }
    }

    // ---- normalize + write ----
    float inv0 = 1.f / l0, inv1 = 1.f / l1;
    float* og = g_attn + (size_t)h * HEADD;
#pragma unroll
    for (int nt = 0; nt < 16; nt++) {
        int c = nt * 8 + cq * 2;
        float2 v0 = {O[nt][0] * inv0, O[nt][1] * inv0};
        float2 v1 = {O[nt][2] * inv1, O[nt][3] * inv1};
        *(float2*)(og + (size_t)q0 * DMODEL + c) = v0;
        *(float2*)(og + (size_t)q1 * DMODEL + c) = v1;
    }
}

// ---------------- launch ----------------
extern "C" void kernel_launch(void* const* d_in, const int* in_sizes, int n_in,
                              void* d_out, int out_size) {
    const float* hidden    = (const float*)d_in[0];
    const float* sink_k    = (const float*)d_in[1];
    const float* sink_v    = (const float*)d_in[2];
    const float* win_k     = (const float*)d_in[3];
    const float* win_v     = (const float*)d_in[4];
    const int*   sink_pos  = (const int*)d_in[5];
    const int*   key_pos   = (const int*)d_in[6];
    const float* sink_mask = (const float*)d_in[7];
    const float* key_mask  = (const float*)d_in[8];
    const float* Wq        = (const float*)d_in[9];
    const float* Wk        = (const float*)d_in[10];
    const float* Wv        = (const float*)d_in[11];
    const float* Wo        = (const float*)d_in[12];
    float*       out       = (float*)d_out;

    float *pq, *pk, *pv, *pattn;
    cudaGetSymbolAddress((void**)&pq, g_q);
    cudaGetSymbolAddress((void**)&pk, g_kproj);
    cudaGetSymbolAddress((void**)&pv, g_vproj);
    cudaGetSymbolAddress((void**)&pattn, g_attn);

    static bool attr_set = false;
    if (!attr_set) {
        cudaFuncSetAttribute(attn_mma_kernel,
                             cudaFuncAttributeMaxDynamicSharedMemorySize,
                             ATTN_SMEM_BYTES);
        attr_set = true;
    }

    maxpos_kernel<<<1, 256>>>(sink_pos, key_pos);
    bias_kernel<<<(NSNW + 255) / 256, 256>>>(sink_mask, key_mask);

    // projections (tensor cores, tf32)
    gemm_tf32<<<dim3(DMODEL / 128, QLEN / 128), 256>>>(hidden, Wq, pq, QLEN, DMODEL, DMODEL);
    gemm_tf32<<<dim3(KVDIM / 128, QLEN / 128), 256>>>(hidden, Wk, pk, QLEN, KVDIM, DMODEL);
    gemm_tf32<<<dim3(KVDIM / 128, QLEN / 128), 256>>>(hidden, Wv, pv, QLEN, KVDIM, DMODEL);

    // RoPE + cache assembly (tf32-rounded; K d-interleaved)
    rope_q_kernel<<<(QLEN * NHEAD * 64 + 255) / 256, 256>>>();
    build_cache_kernel<<<(NKVH * KTOT * 64 + 255) / 256, 256>>>(
        sink_k, sink_v, win_k, win_v, sink_pos, key_pos);

    // attention (tf32 mma flash, bulk-async double-buffered K/V)
    attn_mma_kernel<<<dim3(NHEAD, QLEN / 128), 256, ATTN_SMEM_BYTES>>>();

    // output projection
    gemm_tf32<<<dim3(DMODEL / 128, QLEN / 128), 256>>>(pattn, Wo, out, QLEN, DMODEL, DMODEL);
}

// round 7
// speedup vs baseline: 1.1015x; 1.1015x over previous
#include <cuda_runtime.h>
#include <cuda_bf16.h>
#include <cstdint>

// ---------------- Problem constants ----------------
#define QLEN   2048
#define DMODEL 4096
#define NHEAD  32
#define NKVH   8
#define HEADD  128
#define NSINK  4
#define NWIN   2048
#define NSNW   (NSINK + NWIN)          // 2052
#define KTOT   (NSNW + QLEN)           // 4100
#define GRP    (NHEAD / NKVH)          // 4
#define KVDIM  (NKVH * HEADD)          // 1024

#define NEG_BIG (-3.4028234663852886e38f)   // finfo(float32).min
#define LOG10000_OVER_64 0.14391156831212787f
#define ATTN_SCALE 0.08838834764831845f     // 1/sqrt(128)

// ---------------- Scratch (device globals; no runtime alloc) ----------------
__device__ float g_q[QLEN * DMODEL];        // q proj -> RoPE'd, tf32-rounded
__device__ float g_kproj[QLEN * KVDIM];
__device__ float g_vproj[QLEN * KVDIM];
__device__ float g_K[NKVH * KTOT * HEADD + 64 * HEADD];  // RoPE'd K, d-interleaved, tf32
__device__ float g_V[NKVH * KTOT * HEADD + 64 * HEADD];  // V cache, tf32
__device__ float g_attn[QLEN * DMODEL];     // attention output (pre-Wo)
__device__ float g_bias[NSNW];              // cache bias (mask * NEG)
__device__ int   g_maxpos;

__device__ __forceinline__ float neg_inf() { return __int_as_float(0xff800000u); }

// column interleave within each 8-block: pairs (c, c+4) adjacent
__device__ __forceinline__ int perm8(int d) {
    return (d & ~7) | ((d & 3) << 1) | ((d >> 2) & 1);
}

__device__ __forceinline__ uint32_t f2tf32(float x) {
    uint32_t u;
    asm("cvt.rna.tf32.f32 %0, %1;" : "=r"(u) : "f"(x));
    return u;
}
__device__ __forceinline__ float f2tf32f(float x) {
    return __uint_as_float(f2tf32(x));
}

__device__ __forceinline__ void mma_tf32(float d[4],
                                         uint32_t a0, uint32_t a1, uint32_t a2, uint32_t a3,
                                         uint32_t b0, uint32_t b1) {
    asm volatile(
        "mma.sync.aligned.m16n8k8.row.col.f32.tf32.tf32.f32 "
        "{%0,%1,%2,%3}, {%4,%5,%6,%7}, {%8,%9}, {%0,%1,%2,%3};\n"
        : "+f"(d[0]), "+f"(d[1]), "+f"(d[2]), "+f"(d[3])
        : "r"(a0), "r"(a1), "r"(a2), "r"(a3), "r"(b0), "r"(b1));
}

__device__ __forceinline__ void cp16(uint32_t dst, const float* src, bool v) {
    asm volatile("cp.async.cg.shared.global [%0], [%1], 16, %2;\n"
                 :: "r"(dst), "l"(src), "r"(v ? 16 : 0) : "memory");
}
__device__ __forceinline__ void cp_commit() {
    asm volatile("cp.async.commit_group;\n" ::: "memory");
}
__device__ __forceinline__ void cp_wait0() {
    asm volatile("cp.async.wait_group 0;\n" ::: "memory");
}

// ---------------- max position + bias precompute ----------------
__global__ void maxpos_kernel(const int* __restrict__ sink_pos,
                              const int* __restrict__ key_pos) {
    __shared__ int sm[256];
    int tid = threadIdx.x;
    int v = -2147483647;
    for (int i = tid; i < NWIN; i += 256) v = max(v, key_pos[i]);
    for (int i = tid; i < NSINK; i += 256) v = max(v, sink_pos[i]);
    sm[tid] = v;
    __syncthreads();
    for (int s = 128; s > 0; s >>= 1) {
        if (tid < s) sm[tid] = max(sm[tid], sm[tid + s]);
        __syncthreads();
    }
    if (tid == 0) g_maxpos = sm[0] + 1;
}

__global__ void bias_kernel(const float* __restrict__ sink_mask,
                            const float* __restrict__ key_mask) {
    int i = blockIdx.x * blockDim.x + threadIdx.x;
    if (i >= NSNW) return;
    float m = (i < NSINK) ? sink_mask[i] : key_mask[i - NSINK];
    g_bias[i] = m * NEG_BIG;
}

// ---------------- TF32 GEMM body: software-pipelined (LDG t+1 over compute t) ----------------
#define GSTR 136
struct GemmSmem {
    uint32_t As[32][GSTR];
    uint32_t Bs[32][GSTR];
};

__device__ __forceinline__ void gemm_body(
    const float* __restrict__ A, const float* __restrict__ B,
    float* __restrict__ C, int N, int K, int cRow, int cCol, GemmSmem& sm) {
    const int tid  = threadIdx.x;
    const int lane = tid & 31;
    const int warp = tid >> 5;
    const int wm   = (warp >> 1) * 32;
    const int wn   = (warp & 1) * 64;
    const int r0   = lane >> 2;
    const int cq   = lane & 3;

    float acc[2][8][4];
#pragma unroll
    for (int mt = 0; mt < 2; mt++)
#pragma unroll
        for (int nt = 0; nt < 8; nt++)
#pragma unroll
            for (int f = 0; f < 4; f++) acc[mt][nt][f] = 0.f;

    // per-thread load coordinates
    const int arA = (tid * 4) >> 5;          // row stride pattern base
    float4 pa[4], pb[4];

    // prologue: load + store tile 0
#pragma unroll
    for (int i = 0; i < 4; i++) {
        int e = (i * 256 + tid) * 4;
        int r = e >> 5, c = e & 31;
        pa[i] = *(const float4*)(A + (size_t)(cRow + r) * K + c);
        int rb = e >> 7, cb = e & 127;
        pb[i] = *(const float4*)(B + (size_t)rb * N + cCol + cb);
    }
    (void)arA;
#pragma unroll
    for (int i = 0; i < 4; i++) {
        int e = (i * 256 + tid) * 4;
        int r = e >> 5, c = e & 31;
        sm.As[c + 0][r] = f2tf32(pa[i].x);
        sm.As[c + 1][r] = f2tf32(pa[i].y);
        sm.As[c + 2][r] = f2tf32(pa[i].z);
        sm.As[c + 3][r] = f2tf32(pa[i].w);
        int rb = e >> 7, cb = e & 127;
        uint4 u = {f2tf32(pb[i].x), f2tf32(pb[i].y), f2tf32(pb[i].z), f2tf32(pb[i].w)};
        *(uint4*)&sm.Bs[rb][cb] = u;
    }
    __syncthreads();

    for (int k0 = 0; k0 < K; k0 += 32) {
        const bool more = (k0 + 32) < K;
        if (more) {
#pragma unroll
            for (int i = 0; i < 4; i++) {
                int e = (i * 256 + tid) * 4;
                int r = e >> 5, c = e & 31;
                pa[i] = *(const float4*)(A + (size_t)(cRow + r) * K + k0 + 32 + c);
                int rb = e >> 7, cb = e & 127;
                pb[i] = *(const float4*)(B + (size_t)(k0 + 32 + rb) * N + cCol + cb);
            }
        }

#pragma unroll
        for (int kk = 0; kk < 4; kk++) {
            const int kb = kk * 8;
            uint32_t af[2][4];
#pragma unroll
            for (int mt = 0; mt < 2; mt++) {
                int mr = wm + mt * 16 + r0;
                af[mt][0] = sm.As[kb + cq][mr];
                af[mt][1] = sm.As[kb + cq][mr + 8];
                af[mt][2] = sm.As[kb + 4 + cq][mr];
                af[mt][3] = sm.As[kb + 4 + cq][mr + 8];
            }
#pragma unroll
            for (int nt = 0; nt < 8; nt++) {
                int nc = wn + nt * 8 + r0;
                uint32_t b0 = sm.Bs[kb + cq][nc];
                uint32_t b1 = sm.Bs[kb + 4 + cq][nc];
                mma_tf32(acc[0][nt], af[0][0], af[0][1], af[0][2], af[0][3], b0, b1);
                mma_tf32(acc[1][nt], af[1][0], af[1][1], af[1][2], af[1][3], b0, b1);
            }
        }
        __syncthreads();

        if (more) {
#pragma unroll
            for (int i = 0; i < 4; i++) {
                int e = (i * 256 + tid) * 4;
                int r = e >> 5, c = e & 31;
                sm.As[c + 0][r] = f2tf32(pa[i].x);
                sm.As[c + 1][r] = f2tf32(pa[i].y);
                sm.As[c + 2][r] = f2tf32(pa[i].z);
                sm.As[c + 3][r] = f2tf32(pa[i].w);
                int rb = e >> 7, cb = e & 127;
                uint4 u = {f2tf32(pb[i].x), f2tf32(pb[i].y), f2tf32(pb[i].z), f2tf32(pb[i].w)};
                *(uint4*)&sm.Bs[rb][cb] = u;
            }
            __syncthreads();
        }
    }

#pragma unroll
    for (int mt = 0; mt < 2; mt++)
#pragma unroll
        for (int nt = 0; nt < 8; nt++) {
            int r = cRow + wm + mt * 16 + r0;
            int c = cCol + wn + nt * 8 + cq * 2;
            float2 v0 = {acc[mt][nt][0], acc[mt][nt][1]};
            float2 v1 = {acc[mt][nt][2], acc[mt][nt][3]};
            *(float2*)(C + (size_t)r * N + c)       = v0;
            *(float2*)(C + (size_t)(r + 8) * N + c) = v1;
        }
}

__global__ void __launch_bounds__(256) gemm_tf32(
    const float* __restrict__ A, const float* __restrict__ B,
    float* __restrict__ C, int N, int K) {
    __shared__ GemmSmem sm;
    gemm_body(A, B, C, N, K, blockIdx.y * 128, blockIdx.x * 128, sm);
}

// fused Wk|Wv projection: grid (16, 16); x<8 -> K proj, x>=8 -> V proj
__global__ void __launch_bounds__(256) gemm_tf32_kv(
    const float* __restrict__ A,
    const float* __restrict__ Bk, const float* __restrict__ Bv,
    float* __restrict__ Ck, float* __restrict__ Cv) {
    __shared__ GemmSmem sm;
    const bool isV = blockIdx.x >= 8;
    const float* B = isV ? Bv : Bk;
    float* C       = isV ? Cv : Ck;
    const int cCol = (blockIdx.x & 7) * 128;
    gemm_body(A, B, C, KVDIM, DMODEL, blockIdx.y * 128, cCol, sm);
}

// ---------------- RoPE on q (in place, writes tf32-rounded) ----------------
__global__ void rope_q_kernel() {
    int idx = blockIdx.x * blockDim.x + threadIdx.x;
    if (idx >= QLEN * NHEAD * 64) return;
    int i  = idx & 63;
    int hq = idx >> 6;
    int h  = hq & (NHEAD - 1);
    int t  = hq >> 5;
    float* p = g_q + (size_t)t * DMODEL + h * HEADD;
    float pos = (float)(g_maxpos + t);
    float freq = expf(-(float)i * LOG10000_OVER_64);
    float ang = pos * freq;
    float c, s;
    sincosf(ang, &s, &c);
    float x1 = p[i], x2 = p[i + 64];
    p[i]      = f2tf32f(x1 * c - x2 * s);
    p[i + 64] = f2tf32f(x2 * c + x1 * s);
}

// ---------------- Build concatenated K (RoPE'd, d-interleaved) and V caches ----------------
__global__ void build_cache_kernel(const float* __restrict__ sink_k,
                                   const float* __restrict__ sink_v,
                                   const float* __restrict__ win_k,
                                   const float* __restrict__ win_v,
                                   const int* __restrict__ sink_pos,
                                   const int* __restrict__ key_pos) {
    int idx = blockIdx.x * blockDim.x + threadIdx.x;
    if (idx >= NKVH * KTOT * 64) return;
    int i   = idx & 63;
    int rj  = idx >> 6;
    int j   = rj % KTOT;
    int kvh = rj / KTOT;

    const float* kp;
    const float* vp;
    int pos;
    if (j < NSINK) {
        kp = sink_k + (size_t)(kvh * NSINK + j) * HEADD;
        vp = sink_v + (size_t)(kvh * NSINK + j) * HEADD;
        pos = sink_pos[j];
    } else if (j < NSNW) {
        int w = j - NSINK;
        kp = win_k + (size_t)(kvh * NWIN + w) * HEADD;
        vp = win_v + (size_t)(kvh * NWIN + w) * HEADD;
        pos = key_pos[w];
    } else {
        int t = j - NSNW;
        kp = g_kproj + (size_t)t * KVDIM + kvh * HEADD;
        vp = g_vproj + (size_t)t * KVDIM + kvh * HEADD;
        pos = g_maxpos + t;
    }

    float freq = expf(-(float)i * LOG10000_OVER_64);
    float ang = (float)pos * freq;
    float c, s;
    sincosf(ang, &s, &c);
    float x1 = kp[i], x2 = kp[i + 64];

    size_t out = ((size_t)kvh * KTOT + j) * HEADD;
    g_K[out + perm8(i)]      = f2tf32f(x1 * c - x2 * s);
    g_K[out + perm8(i + 64)] = f2tf32f(x2 * c + x1 * s);
    g_V[out + i]      = f2tf32f(vp[i]);
    g_V[out + i + 64] = f2tf32f(vp[i + 64]);
}

// ---------------- Flash attention: cp.async K/V, LDS.64 frags, reg-pipelined ----------------
// Smem word layout (dynamic):
//   buf0: Ks0[64][136] @ 0        Vs0[64][136] @ 8704
//   buf1: Ks1[64][136] @ 17408    Vs1[64][136] @ 26112
//   (Q staged in buf1 region during prologue: 128*136 = 17408 words, exact fit)
//   Ps[128][68] @ 34816 (8704 w)
#define KS_STR 136
#define VS_STR 136
#define PS_STR 68
#define BUF_WORDS (64 * KS_STR + 64 * VS_STR)      // 17408
#define PS_OFF    (2 * BUF_WORDS)                   // 34816
#define ATTN_SMEM_BYTES ((PS_OFF + 128 * PS_STR) * 4)

__global__ void __launch_bounds__(256, 1) attn_mma_kernel() {
    extern __shared__ uint32_t smw[];
    const uint32_t smem_base = (uint32_t)__cvta_generic_to_shared(smw);

    const int h    = blockIdx.x;
    const int kvh  = h >> 2;                              // GRP = 4
    const int qt0  = (gridDim.y - 1 - blockIdx.y) * 128;  // long blocks first
    const int tid  = threadIdx.x;
    const int lane = tid & 31;
    const int warp = tid >> 5;
    const int qw   = warp * 16;
    const int r0   = lane >> 2;
    const int cq   = lane & 3;

    const float* Kg = g_K + (size_t)kvh * KTOT * HEADD;
    const float* Vg = g_V + (size_t)kvh * KTOT * HEADD;

    int kmax = NSNW + qt0 + 128;
    if (kmax > KTOT) kmax = KTOT;
    const int ntiles = (kmax + 63) >> 6;

    // ---- prefetch tile 0 into buf0 ----
    {
        uint32_t kbase = smem_base;
        uint32_t vbase = smem_base + 64 * KS_STR * 4;
        for (int i = tid; i < 2048; i += 256) {
            int key = i >> 5, c = i & 31;
            bool v = (key < KTOT);
            cp16(kbase + (key * KS_STR + c * 4) * 4, Kg + (size_t)key * HEADD + c * 4, v);
            cp16(vbase + (key * VS_STR + c * 4) * 4, Vg + (size_t)key * HEADD + c * 4, v);
        }
        cp_commit();
    }

    // ---- stage Q tile [128q][128d] into buf1 region, d-interleaved ----
    {
        uint32_t* Qs = smw + BUF_WORDS;
        const float* qg = g_q + (size_t)qt0 * DMODEL + h * HEADD;
        for (int i = tid; i < 128 * 32; i += 256) {
            int q = i >> 5, c4 = (i & 31) * 4;
            float4 v = *(const float4*)(qg + (size_t)q * DMODEL + c4);
            uint32_t* qrow = Qs + q * KS_STR;
            qrow[perm8(c4 + 0)] = __float_as_uint(v.x);
            qrow[perm8(c4 + 1)] = __float_as_uint(v.y);
            qrow[perm8(c4 + 2)] = __float_as_uint(v.z);
            qrow[perm8(c4 + 3)] = __float_as_uint(v.w);
        }
    }
    __syncthreads();

    // ---- extract Q fragments to registers (LDS.64 pairs) ----
    uint32_t QA[16][4];
    {
        const uint32_t* Qs = smw + BUF_WORDS;
#pragma unroll
        for (int kk = 0; kk < 16; kk++) {
            uint2 u0 = *(const uint2*)&Qs[(qw + r0) * KS_STR + kk * 8 + 2 * cq];
            uint2 u1 = *(const uint2*)&Qs[(qw + r0 + 8) * KS_STR + kk * 8 + 2 * cq];
            QA[kk][0] = u0.x; QA[kk][1] = u1.x;
            QA[kk][2] = u0.y; QA[kk][3] = u1.y;
        }
    }
    __syncthreads();

    float O[16][4];
#pragma unroll
    for (int nt = 0; nt < 16; nt++)
#pragma unroll
        for (int f = 0; f < 4; f++) O[nt][f] = 0.f;
    float m0 = neg_inf(), m1 = neg_inf(), l0 = 0.f, l1 = 0.f;

    const int q0 = qt0 + qw + r0;
    const int q1 = q0 + 8;

    for (int t = 0; t < ntiles; t++) {
        const int j0 = t * 64;
        const int buf = t & 1;
        const uint32_t* Ks = smw + buf * BUF_WORDS;
        const uint32_t* Vs = Ks + 64 * KS_STR;
        uint32_t* Ps = smw + PS_OFF;

        cp_wait0();
        __syncthreads();

        // prefetch next tile into the other buffer
        if (t + 1 < ntiles) {
            const int jn = j0 + 64;
            uint32_t kbase = smem_base + (buf ^ 1) * BUF_WORDS * 4;
            uint32_t vbase = kbase + 64 * KS_STR * 4;
            for (int i = tid; i < 2048; i += 256) {
                int key = i >> 5, c = i & 31;
                int j = jn + key;
                bool v = (j < KTOT);
                int jc = v ? j : (KTOT - 1);
                cp16(kbase + (key * KS_STR + c * 4) * 4, Kg + (size_t)jc * HEADD + c * 4, v);
                cp16(vbase + (key * VS_STR + c * 4) * 4, Vg + (size_t)jc * HEADD + c * 4, v);
            }
            cp_commit();
        }

        // preload bias for this tile's columns
        float bb[8][2];
#pragma unroll
        for (int nt = 0; nt < 8; nt++) {
            int ja = j0 + nt * 8 + cq * 2;
            bb[nt][0] = (ja < NSNW) ? g_bias[ja] : 0.f;
            bb[nt][1] = (ja + 1 < NSNW) ? g_bias[ja + 1] : 0.f;
        }

        // ---- S = Q @ K^T  (16 x 64 per warp), B-frags double-buffered in regs ----
        float S[8][4];
#pragma unroll
        for (int nt = 0; nt < 8; nt++)
#pragma unroll
            for (int f = 0; f < 4; f++) S[nt][f] = 0.f;

        uint2 bc[8];
#pragma unroll
        for (int nt = 0; nt < 8; nt++)
            bc[nt] = *(const uint2*)&Ks[(nt * 8 + r0) * KS_STR + 2 * cq];

#pragma unroll
        for (int kk = 0; kk < 16; kk++) {
            uint2 bn[8];
            if (kk < 15) {
#pragma unroll
                for (int nt = 0; nt < 8; nt++)
                    bn[nt] = *(const uint2*)&Ks[(nt * 8 + r0) * KS_STR + (kk + 1) * 8 + 2 * cq];
            }
#pragma unroll
            for (int nt = 0; nt < 8; nt++)
                mma_tf32(S[nt], QA[kk][0], QA[kk][1], QA[kk][2], QA[kk][3],
                         bc[nt].x, bc[nt].y);
            if (kk < 15) {
#pragma unroll
                for (int nt = 0; nt < 8; nt++) bc[nt] = bn[nt];
            }
        }

        // ---- online softmax ----
        float rm0 = neg_inf(), rm1 = neg_inf();
#pragma unroll
        for (int nt = 0; nt < 8; nt++) {
            int ja = j0 + nt * 8 + cq * 2;
            int jb = ja + 1;
            float s0 = (ja <= q0 + NSNW) ? S[nt][0] * ATTN_SCALE + bb[nt][0] : neg_inf();
            float s1 = (jb <= q0 + NSNW) ? S[nt][1] * ATTN_SCALE + bb[nt][1] : neg_inf();
            float s2 = (ja <= q1 + NSNW) ? S[nt][2] * ATTN_SCALE + bb[nt][0] : neg_inf();
            float s3 = (jb <= q1 + NSNW) ? S[nt][3] * ATTN_SCALE + bb[nt][1] : neg_inf();
            S[nt][0] = s0; S[nt][1] = s1; S[nt][2] = s2; S[nt][3] = s3;
            rm0 = fmaxf(rm0, fmaxf(s0, s1));
            rm1 = fmaxf(rm1, fmaxf(s2, s3));
        }
        rm0 = fmaxf(rm0, __shfl_xor_sync(0xffffffffu, rm0, 1));
        rm0 = fmaxf(rm0, __shfl_xor_sync(0xffffffffu, rm0, 2));
        rm1 = fmaxf(rm1, __shfl_xor_sync(0xffffffffu, rm1, 1));
        rm1 = fmaxf(rm1, __shfl_xor_sync(0xffffffffu, rm1, 2));

        float mn0 = fmaxf(m0, rm0);
        float mn1 = fmaxf(m1, rm1);
        float mns0 = (mn0 == neg_inf()) ? 0.f : mn0;
        float mns1 = (mn1 == neg_inf()) ? 0.f : mn1;
        float f0 = __expf(m0 - mns0);
        float f1 = __expf(m1 - mns1);
        if (m0 == neg_inf()) f0 = 0.f;
        if (m1 == neg_inf()) f1 = 0.f;
        m0 = mn0; m1 = mn1;
        l0 *= f0; l1 *= f1;
#pragma unroll
        for (int nt = 0; nt < 16; nt++) {
            O[nt][0] *= f0; O[nt][1] *= f0;
            O[nt][2] *= f1; O[nt][3] *= f1;
        }

        float ps0 = 0.f, ps1 = 0.f;
#pragma unroll
        for (int nt = 0; nt < 8; nt++) {
            int col = nt * 8 + cq * 2;
            float p0 = __expf(S[nt][0] - mns0);
            float p1 = __expf(S[nt][1] - mns0);
            float p2 = __expf(S[nt][2] - mns1);
            float p3 = __expf(S[nt][3] - mns1);
            ps0 += p0 + p1;
            ps1 += p2 + p3;
            *(uint2*)&Ps[(qw + r0) * PS_STR + col]     = make_uint2(f2tf32(p0), f2tf32(p1));
            *(uint2*)&Ps[(qw + r0 + 8) * PS_STR + col] = make_uint2(f2tf32(p2), f2tf32(p3));
        }
        ps0 += __shfl_xor_sync(0xffffffffu, ps0, 1);
        ps0 += __shfl_xor_sync(0xffffffffu, ps0, 2);
        ps1 += __shfl_xor_sync(0xffffffffu, ps1, 1);
        ps1 += __shfl_xor_sync(0xffffffffu, ps1, 2);
        l0 += ps0; l1 += ps1;

        __syncwarp();

        // ---- O += P @ V (A-frags prefetched one kk ahead) ----
        uint32_t ac[4];
        ac[0] = Ps[(qw + r0) * PS_STR + cq];
        ac[1] = Ps[(qw + r0 + 8) * PS_STR + cq];
        ac[2] = Ps[(qw + r0) * PS_STR + cq + 4];
        ac[3] = Ps[(qw + r0 + 8) * PS_STR + cq + 4];
#pragma unroll
        for (int kk = 0; kk < 8; kk++) {
            const int kb = kk * 8;
            uint32_t an[4];
            if (kk < 7) {
                an[0] = Ps[(qw + r0) * PS_STR + kb + 8 + cq];
                an[1] = Ps[(qw + r0 + 8) * PS_STR + kb + 8 + cq];
                an[2] = Ps[(qw + r0) * PS_STR + kb + 8 + cq + 4];
                an[3] = Ps[(qw + r0 + 8) * PS_STR + kb + 8 + cq + 4];
            }
#pragma unroll
            for (int nt = 0; nt < 16; nt++) {
                uint32_t b0 = Vs[(kb + cq) * VS_STR + nt * 8 + r0];
                uint32_t b1 = Vs[(kb + cq + 4) * VS_STR + nt * 8 + r0];
                mma_tf32(O[nt], ac[0], ac[1], ac[2], ac[3], b0, b1);
            }
            if (kk < 7) {
                ac[0] = an[0]; ac[1] = an[1]; ac[2] = an[2]; ac[3] = an[3];
            }
        }
    }

    // ---- normalize + write ----
    float inv0 = 1.f / l0, inv1 = 1.f / l1;
    float* og = g_attn + (size_t)h * HEADD;
#pragma unroll
    for (int nt = 0; nt < 16; nt++) {
        int c = nt * 8 + cq * 2;
        float2 v0 = {O[nt][0] * inv0, O[nt][1] * inv0};
        float2 v1 = {O[nt][2] * inv1, O[nt][3] * inv1};
        *(float2*)(og + (size_t)q0 * DMODEL + c) = v0;
        *(float2*)(og + (size_t)q1 * DMODEL + c) = v1;
    }
}

// ---------------- launch ----------------
extern "C" void kernel_launch(void* const* d_in, const int* in_sizes, int n_in,
                              void* d_out, int out_size) {
    const float* hidden    = (const float*)d_in[0];
    const float* sink_k    = (const float*)d_in[1];
    const float* sink_v    = (const float*)d_in[2];
    const float* win_k     = (const float*)d_in[3];
    const float* win_v     = (const float*)d_in[4];
    const int*   sink_pos  = (const int*)d_in[5];
    const int*   key_pos   = (const int*)d_in[6];
    const float* sink_mask = (const float*)d_in[7];
    const float* key_mask  = (const float*)d_in[8];
    const float* Wq        = (const float*)d_in[9];
    const float* Wk        = (const float*)d_in[10];
    const float* Wv        = (const float*)d_in[11];
    const float* Wo        = (const float*)d_in[12];
    float*       out       = (float*)d_out;

    float *pq, *pk, *pv, *pattn;
    cudaGetSymbolAddress((void**)&pq, g_q);
    cudaGetSymbolAddress((void**)&pk, g_kproj);
    cudaGetSymbolAddress((void**)&pv, g_vproj);
    cudaGetSymbolAddress((void**)&pattn, g_attn);

    static bool attr_set = false;
    if (!attr_set) {
        cudaFuncSetAttribute(attn_mma_kernel,
                             cudaFuncAttributeMaxDynamicSharedMemorySize,
                             ATTN_SMEM_BYTES);
        attr_set = true;
    }

    maxpos_kernel<<<1, 256>>>(sink_pos, key_pos);
    bias_kernel<<<(NSNW + 255) / 256, 256>>>(sink_mask, key_mask);

    // projections (tensor cores, tf32, pipelined)
    gemm_tf32<<<dim3(DMODEL / 128, QLEN / 128), 256>>>(hidden, Wq, pq, DMODEL, DMODEL);
    gemm_tf32_kv<<<dim3(16, QLEN / 128), 256>>>(hidden, Wk, Wv, pk, pv);

    // RoPE + cache assembly (tf32-rounded; K d-interleaved)
    rope_q_kernel<<<(QLEN * NHEAD * 64 + 255) / 256, 256>>>();
    build_cache_kernel<<<(NKVH * KTOT * 64 + 255) / 256, 256>>>(
        sink_k, sink_v, win_k, win_v, sink_pos, key_pos);

    // attention (tf32 mma flash, cp.async double-buffered K/V)
    attn_mma_kernel<<<dim3(NHEAD, QLEN / 128), 256, ATTN_SMEM_BYTES>>>();

    // output projection
    gemm_tf32<<<dim3(DMODEL / 128, QLEN / 128), 256>>>(pattn, Wo, out, DMODEL, DMODEL);
}